// round 8
// baseline (speedup 1.0000x reference)
#include <cuda_runtime.h>
#include <cuda_bf16.h>

// VanillaRNN diagonal recurrence, f32. Evidence (R5 fma=20.6% @ 2 FFMA/step)
// says FFMA effective rt ~1/SMSP on sm_103a, so the FMA port has 2x the
// headroom my earlier rt2 model assumed. Raise tanh offload to beta=3/16:
// MUFU 92K cyc/SMSP vs FMA ~73K -> MUFU still (barely) binding, ~10% faster.
// f16 state fatal (R4); all state f32.

#define RB 1024   // batch
#define RT 1024   // time steps
#define RH 256    // hidden
#define RC 10     // classes

__device__ __forceinline__ float tanh_hw(float x) {
    float r;
    asm("tanh.approx.f32 %0, %1;" : "=f"(r) : "f"(x));
    return r;
}

// Lean all-FMA/ALU tanh: ~17 FMA-pipe + ~4 ALU-pipe ops, |err| ~4e-5 abs.
// tanh(z) = sign(z)*(1 - 2e/(1+e)), e = 2^w, w = -2|z|/ln2 = k + r.
__device__ __forceinline__ float tanh_fma(float z) {
    const float NL2E2 = -2.885390081777927f;   // -2/ln2
    const float MAGIC = 12582912.0f;           // 1.5 * 2^23
    float az = fminf(fabsf(z), 40.0f);         // FMNMX (alu)
    float t  = fmaf(az, NL2E2, MAGIC);         // rounded w in low bits
    float kf = t - MAGIC;                      // k = rint(w)
    float r  = fmaf(az, NL2E2, -kf);           // r in [-0.5, 0.5]
    float sc = __int_as_float((__float_as_int(t) + (127 - 0x4B400000)) << 23); // 2^k
    // 2^r Taylor deg-4, Estrin
    float r2 = r * r;
    float q0 = fmaf(0.6931471806f, r, 1.0f);
    float q1 = fmaf(0.0555041087f, r, 0.2402265070f);
    float qq = fmaf(0.0096181291f, r2, q1);
    float p  = fmaf(qq, r2, q0);
    float e  = p * sc;                         // e^{-2|z|} in (0, 1]
    float den = e + 1.0f;                      // [1, 2]
    float y  = fmaf(den, -0.5f, 1.45710678f);  // linear seed
    y = y * fmaf(-den, y, 2.0f);               // Newton 1
    y = y * fmaf(-den, y, 2.0f);               // Newton 2
    float e2 = e + e;
    float res = fmaf(-e2, y, 1.0f);            // 1 - 2e/(1+e)
    return copysignf(res, z);                  // LOP3 (alu)
}

__global__ __launch_bounds__(RH, 7)
void vanilla_rnn_kernel(const float* __restrict__ x,
                        const float* __restrict__ W_hx,
                        const float* __restrict__ W_hh,
                        const float* __restrict__ b_h,
                        const float* __restrict__ W_hp,
                        const float* __restrict__ b_o,
                        float* __restrict__ out)
{
    __shared__ float4 xs4[RT / 4];   // this block's x row (4 KB)
    __shared__ float  hs[RH];        // final hidden state for epilogue

    const int b = blockIdx.x;
    const int h = threadIdx.x;

    {
        const float4* xrow = reinterpret_cast<const float4*>(x + (size_t)b * RT);
        xs4[h] = xrow[h];
    }

    const float wi = W_hx[h];
    const float wd = W_hh[h * RH + h];
    const float bh = b_h[h];

    __syncthreads();

    float hv = 0.0f;
    // 64 chunks x 16 steps (4 float4 loads). Steps 5, 10, 15 of each chunk on
    // the FMA pipe -> beta = 3/16 = 0.1875, uniform across all SMSPs.
    #pragma unroll 1
    for (int c = 0; c < 64; c++) {
        const int q = c * 4;
        #pragma unroll
        for (int s4 = 0; s4 < 4; s4++) {
            float4 xv = xs4[q + s4];
            float a0 = fmaf(xv.x, wi, bh);
            float a1 = fmaf(xv.y, wi, bh);
            float a2 = fmaf(xv.z, wi, bh);
            float a3 = fmaf(xv.w, wi, bh);
            // step indices s4*4 + {0,1,2,3}; offload at 5, 10, 15
            if (s4 == 1)
                hv = tanh_fma(fmaf(hv, wd, a0));      // step 4? no: idx 4 -> keep
            else
                hv = tanh_hw (fmaf(hv, wd, a0));
            hv = tanh_hw(fmaf(hv, wd, a1));
            if (s4 == 2)
                hv = tanh_fma(fmaf(hv, wd, a2));      // step 10
            else
                hv = tanh_hw (fmaf(hv, wd, a2));
            if (s4 == 3)
                hv = tanh_fma(fmaf(hv, wd, a3));      // step 15
            else
                hv = tanh_hw (fmaf(hv, wd, a3));
        }
    }

    hs[h] = hv;
    __syncthreads();

    if (h < RC) {
        const float* wrow = W_hp + h * RH;
        float acc = b_o[h];
        #pragma unroll 8
        for (int j = 0; j < RH; j++)
            acc = fmaf(hs[j], wrow[j], acc);
        out[b * RC + h] = acc;
    }
}

extern "C" void kernel_launch(void* const* d_in, const int* in_sizes, int n_in,
                              void* d_out, int out_size)
{
    const float* x    = (const float*)d_in[0];
    const float* W_hx = (const float*)d_in[1];
    const float* W_hh = (const float*)d_in[2];
    const float* b_h  = (const float*)d_in[3];
    const float* W_hp = (const float*)d_in[4];
    const float* b_o  = (const float*)d_in[5];
    float* out = (float*)d_out;

    vanilla_rnn_kernel<<<RB, RH>>>(x, W_hx, W_hh, b_h, W_hp, b_o, out);
}

// round 9
// speedup vs baseline: 1.0097x; 1.0097x over previous
#include <cuda_runtime.h>
#include <cuda_bf16.h>

// VanillaRNN diagonal recurrence, f32. Discriminating experiment: is the
// kernel truly MUFU-port-bound (rt 8) or latency-bound with headroom?
// ILP=2 per thread (same h, two batch rows) at the proven 256-thread block
// shape (R3's ILP=2 failed on residency, occ 29%, not on instruction mix).
// Per-SMSP MUFU work identical to R5; if port-bound -> neutral, if
// latency-bound -> up to 2x. f16 state fatal (R4); all state f32.

#define RB 1024   // batch
#define RT 1024   // time steps
#define RH 256    // hidden
#define RC 10     // classes

__device__ __forceinline__ float tanh_hw(float x) {
    float r;
    asm("tanh.approx.f32 %0, %1;" : "=f"(r) : "f"(x));
    return r;
}

__global__ __launch_bounds__(RH, 7)
void vanilla_rnn_kernel(const float* __restrict__ x,
                        const float* __restrict__ W_hx,
                        const float* __restrict__ W_hh,
                        const float* __restrict__ b_h,
                        const float* __restrict__ W_hp,
                        const float* __restrict__ b_o,
                        float* __restrict__ out)
{
    __shared__ float2 xs2[RT];       // {x[b0,t], x[b1,t]} packed, 8 KB
    __shared__ float  hs[2][RH];     // final hidden states for both rows

    const int b0 = blockIdx.x * 2;
    const int h  = threadIdx.x;

    // Stage both rows: thread h covers t = 4h .. 4h+3.
    {
        const float4* r0 = reinterpret_cast<const float4*>(x + (size_t)b0 * RT);
        const float4* r1 = reinterpret_cast<const float4*>(x + (size_t)(b0 + 1) * RT);
        float4 a = r0[h];
        float4 c = r1[h];
        const int t = h * 4;
        xs2[t + 0] = make_float2(a.x, c.x);
        xs2[t + 1] = make_float2(a.y, c.y);
        xs2[t + 2] = make_float2(a.z, c.z);
        xs2[t + 3] = make_float2(a.w, c.w);
    }

    const float wi = W_hx[h];
    const float wd = W_hh[h * RH + h];
    const float bh = b_h[h];

    __syncthreads();

    float hv0 = 0.0f, hv1 = 0.0f;
    #pragma unroll 8
    for (int t = 0; t < RT; t++) {
        float2 xv = xs2[t];
        float a0 = fmaf(xv.x, wi, bh);   // t-only, off the carried chain
        float a1 = fmaf(xv.y, wi, bh);
        hv0 = tanh_hw(fmaf(hv0, wd, a0));
        hv1 = tanh_hw(fmaf(hv1, wd, a1));
    }

    hs[0][h] = hv0;
    hs[1][h] = hv1;
    __syncthreads();

    // Epilogue: out[b0+r, c] = sum_h hs[r][h] * W_hp[c, h] + b_o[c]
    if (h < 2 * RC) {
        const int r = h / RC;
        const int c = h % RC;
        const float* wrow = W_hp + c * RH;
        const float* hrow = hs[r];
        float acc = b_o[c];
        #pragma unroll 8
        for (int j = 0; j < RH; j++)
            acc = fmaf(hrow[j], wrow[j], acc);
        out[(b0 + r) * RC + c] = acc;
    }
}

extern "C" void kernel_launch(void* const* d_in, const int* in_sizes, int n_in,
                              void* d_out, int out_size)
{
    const float* x    = (const float*)d_in[0];
    const float* W_hx = (const float*)d_in[1];
    const float* W_hh = (const float*)d_in[2];
    const float* b_h  = (const float*)d_in[3];
    const float* W_hp = (const float*)d_in[4];
    const float* b_o  = (const float*)d_in[5];
    float* out = (float*)d_out;

    vanilla_rnn_kernel<<<RB / 2, RH>>>(x, W_hx, W_hh, b_h, W_hp, b_o, out);
}